// round 11
// baseline (speedup 1.0000x reference)
#include <cuda_runtime.h>
#include <cuda_fp16.h>
#include <cstdint>

// ============================================================================
// LSTM decoder, B=2048, T=32, H=1024, inference path (pred feedback).
// sm_100: fp16 mma.sync GEMM + cp.async 3-stage pipeline, 2 CTAs/SM (R5
// champion GEMM config) + R10 PDL + R11 fine-grained cross-step sync:
//  - NO griddepcontrol.wait. Step t+1 CTA (bx,by) spins on g_flags[t][bx]==32
//    (its 32 true producers) after prefetching B; launch_dependents fires
//    right after, so step grids cascade and epilogue/tail of step t overlaps
//    the GEMM of step t+1.
//  - predsum folded into d_out (init = fc_b in prep; prev read from d_out).
//  - bias/w0/w1/fcW staged in smem (loaded pre-wait, step-invariant).
// W columns permuted: col n -> (unit n>>2, gate n&3), gate order i,f,g,o.
// h double-buffered across steps.
// ============================================================================

#define BATCH 2048
#define TT    32
#define HH    1024
#define N4    4096
#define KE    1024            // K = H (single fp16 term)
#define TM    128             // M tile
#define TN    128             // N tile
#define KC    64              // K chunk (fp16) = 128 bytes
#define NCH   (KE / KC)       // 16
#define NTHREADS 256
#define STAGES 3
#define STAGE_BYTES 32768     // A 16KB + B 16KB
#define STAGING_BYTES 2048
#define SMEM_BYTES  (1024 + STAGES * STAGE_BYTES + STAGING_BYTES)  // ~99KB
#define GPITCH 132            // gates smem pitch (floats), conflict-free
#define NBX   (BATCH / TM)    // 16
#define NBY   (N4 / TN)       // 32 producers per (t, bx)

// Scratch (device globals; no allocation allowed)
__device__ __align__(256) __half g_Wext[(size_t)N4 * KE];        // 8 MB
__device__ __align__(256) __half g_Aext[2][(size_t)BATCH * KE];  // 2 x 4 MB
__device__ __align__(256) float g_c[(size_t)BATCH * HH];         // 8 MB
__device__ __align__(256) float g_bias[N4];
__device__ __align__(256) float g_w0[N4];
__device__ __align__(256) float g_w1[N4];
__device__ __align__(256) float g_fcW[HH];
__device__ __align__(256) int g_flags[TT * NBX];                 // per (t, bx)

// ---------------------------------------------------------------------------
// helpers
// ---------------------------------------------------------------------------
__device__ __forceinline__ uint32_t smem_u32(const void* p) {
    uint32_t a;
    asm("{ .reg .u64 t; cvta.to.shared.u64 t, %1; cvt.u32.u64 %0, t; }" : "=r"(a) : "l"(p));
    return a;
}
__device__ __forceinline__ void cp_async16(uint32_t dst, const void* src) {
    asm volatile("cp.async.cg.shared.global [%0], [%1], 16;" :: "r"(dst), "l"(src) : "memory");
}
__device__ __forceinline__ void cp_commit() {
    asm volatile("cp.async.commit_group;" ::: "memory");
}
__device__ __forceinline__ uint32_t sw128(uint32_t off) {
    return off ^ ((off >> 3) & 0x70u);
}
__device__ __forceinline__ void ldsm_x4(uint32_t& r0, uint32_t& r1, uint32_t& r2, uint32_t& r3,
                                        uint32_t addr) {
    asm volatile("ldmatrix.sync.aligned.m8n8.x4.shared.b16 {%0,%1,%2,%3}, [%4];"
                 : "=r"(r0), "=r"(r1), "=r"(r2), "=r"(r3) : "r"(addr));
}
__device__ __forceinline__ void mma_fp16(float* d, const uint32_t* a, const uint32_t* b) {
    asm volatile(
        "mma.sync.aligned.m16n8k16.row.col.f32.f16.f16.f32 "
        "{%0,%1,%2,%3}, {%4,%5,%6,%7}, {%8,%9}, {%0,%1,%2,%3};"
        : "+f"(d[0]), "+f"(d[1]), "+f"(d[2]), "+f"(d[3])
        : "r"(a[0]), "r"(a[1]), "r"(a[2]), "r"(a[3]), "r"(b[0]), "r"(b[1]));
}
__device__ __forceinline__ float sigf(float x) {
    return __fdividef(1.0f, 1.0f + __expf(-x));
}
__device__ __forceinline__ float tanh_f(float x) {
    float xc = fminf(fmaxf(x, -15.0f), 15.0f);
    float e = __expf(2.0f * xc);
    return 1.0f - __fdividef(2.0f, e + 1.0f);
}

// ---------------------------------------------------------------------------
// Prep kernels
// ---------------------------------------------------------------------------
__global__ void prep_weights(const float* __restrict__ W_hh, const float* __restrict__ W_ih,
                             const float* __restrict__ b_ih, const float* __restrict__ b_hh,
                             const float* __restrict__ fc_W) {
    int idx = blockIdx.x * blockDim.x + threadIdx.x;   // 0 .. 4096*1024-1
    int n = idx >> 10, k = idx & 1023;
    int r = (n & 3) * HH + (n >> 2);                   // col n -> orig W_hh row
    g_Wext[(size_t)n * KE + k] = __float2half(W_hh[(size_t)r * HH + k]);
    if (idx < N4) {
        int rr = (idx & 3) * HH + (idx >> 2);
        g_bias[idx] = b_ih[rr] + b_hh[rr];
        g_w0[idx] = W_ih[rr * 2 + 0];
        g_w1[idx] = W_ih[rr * 2 + 1];
    }
    if (idx < HH) g_fcW[idx] = fc_W[idx];
}

__global__ void prep_state(const float* __restrict__ hidden, const float* __restrict__ cell,
                           float* __restrict__ out, const float* __restrict__ fc_b) {
    int idx = blockIdx.x * blockDim.x + threadIdx.x;   // 0 .. 2048*1024-1
    g_c[idx] = cell[idx];
    g_Aext[0][idx] = __float2half(hidden[idx]);
    if (idx < BATCH * TT) out[idx] = fc_b[0];          // predsum accumulates on top
    if (idx < TT * NBX) g_flags[idx] = 0;              // reset every replay
}

// ---------------------------------------------------------------------------
// Step kernel: GEMM (tile 128x128, K=1024) + fused LSTM cell epilogue
// 256 threads = 8 warps; warp tile 64x32: warp_m = wid&1, warp_n = wid>>1.
// ---------------------------------------------------------------------------
__global__ void __launch_bounds__(NTHREADS, 2)
step_kernel(int t, const float* __restrict__ future_fd, float* __restrict__ out) {
    const __half* __restrict__ Asrc = g_Aext[t & 1];
    __half* __restrict__ Adst = g_Aext[(t + 1) & 1];

    extern __shared__ char smem_raw[];
    uint32_t sb = smem_u32(smem_raw);
    uint32_t ab = (sb + 1023u) & ~1023u;
    char* smem = smem_raw + (ab - sb);
    const uint32_t tiles = ab;

    const int tid = threadIdx.x;
    const int wid = tid >> 5;
    const int lid = tid & 31;
    const int wm = wid & 1;          // 0..1  (64-row block)
    const int wn = wid >> 1;         // 0..3  (32-col block)
    const int m0 = blockIdx.x * TM;
    const int n0 = blockIdx.y * TN;
    const int u0 = n0 >> 2;          // first unit of this CTA (32 units)

    // ---- const staging (step-invariant: safe before any cross-step sync) ---
    float4* smB  = (float4*)(smem + STAGES * STAGE_BYTES);   // [32]
    float4* smW0 = smB + 32;
    float4* smW1 = smB + 64;
    float*  smFc = (float*)(smB + 96);                        // [32]
    if (tid < 32)        smB[tid]        = ((const float4*)g_bias)[u0 + tid];
    else if (tid < 64)   smW0[tid - 32]  = ((const float4*)g_w0)[u0 + tid - 32];
    else if (tid < 96)   smW1[tid - 64]  = ((const float4*)g_w1)[u0 + tid - 64];
    else if (tid < 128)  smFc[tid - 96]  = g_fcW[u0 + tid - 96];

    // ---- split chunk loaders ----------------------------------------------
    auto load_A = [&](int c, int s) {
        const int k0 = c * KC;
        const uint32_t base = tiles + s * STAGE_BYTES;
        #pragma unroll
        for (int j = 0; j < 4; j++) {
            int li = tid + j * NTHREADS;
            int ri = li >> 3, q = li & 7;
            uint32_t dst = base + sw128((uint32_t)(ri * 128 + q * 16));
            cp_async16(dst, Asrc + ((size_t)(m0 + ri) * KE + k0 + q * 8));
        }
    };
    auto load_B = [&](int c, int s) {
        const int k0 = c * KC;
        const uint32_t base = tiles + s * STAGE_BYTES + 16384;
        #pragma unroll
        for (int j = 0; j < 4; j++) {
            int li = tid + j * NTHREADS;
            int ri = li >> 3, q = li & 7;
            uint32_t dst = base + sw128((uint32_t)(ri * 128 + q * 16));
            cp_async16(dst, g_Wext + ((size_t)(n0 + ri) * KE + k0 + q * 8));
        }
    };

    // ---- prologue: weight prefetch overlaps producer epilogues -------------
    load_B(0, 0); cp_commit();                 // group: B0
    load_B(1, 1); cp_commit();                 // group: B1

    // Fine-grained cross-step dependency: wait only for our 32 producers.
    if (t > 0) {
        if (tid == 0) {
            const int* f = &g_flags[(t - 1) * NBX + blockIdx.x];
            while (*(volatile const int*)f != NBY) __nanosleep(32);
            __threadfence();   // acquire: producers' h/out/c stores now visible
        }
        __syncthreads();
    }
    // Let the next step's grid spin up ASAP (it throttles on SM slots + flags).
    asm volatile("griddepcontrol.launch_dependents;");

    load_A(0, 0); cp_commit();                 // group: A0
    load_A(1, 1); cp_commit();                 // group: A1

    // ---- lane constants for ldmatrix addressing ----------------------------
    const int a_lr = lid & 15;
    const int a_ch = (lid >> 4) << 4;
    const int b_nr = (lid & 7) + ((lid >> 4) << 3);
    const int b_ch = ((lid >> 3) & 1) << 4;

    float acc[4][4][4];
    #pragma unroll
    for (int i = 0; i < 4; i++)
        #pragma unroll
        for (int j = 0; j < 4; j++)
            #pragma unroll
            for (int r = 0; r < 4; r++) acc[i][j][r] = 0.0f;

    #pragma unroll 1
    for (int c = 0; c < NCH; c++) {
        // iter 0: groups {B0,B1,A0,A1}; wait_group 1 retires B0,B1,A0 -> stage0 ready.
        if (c < NCH - 2) asm volatile("cp.async.wait_group 1;" ::: "memory");
        else             asm volatile("cp.async.wait_group 0;" ::: "memory");
        __syncthreads();

        if (c + 2 < NCH) { load_A(c + 2, (c + 2) % STAGES); load_B(c + 2, (c + 2) % STAGES); cp_commit(); }

        const uint32_t As = tiles + (c % STAGES) * STAGE_BYTES;
        const uint32_t Bs = As + 16384;

        #pragma unroll
        for (int ks = 0; ks < 4; ks++) {
            uint32_t a[4][4], b[4][2];
            #pragma unroll
            for (int mi = 0; mi < 4; mi++) {
                uint32_t off = (uint32_t)((wm * 64 + mi * 16 + a_lr) * 128 + ks * 32 + a_ch);
                ldsm_x4(a[mi][0], a[mi][1], a[mi][2], a[mi][3], As + sw128(off));
            }
            #pragma unroll
            for (int nb = 0; nb < 2; nb++) {
                uint32_t off = (uint32_t)((wn * 32 + nb * 16 + b_nr) * 128 + ks * 32 + b_ch);
                ldsm_x4(b[nb * 2][0], b[nb * 2][1], b[nb * 2 + 1][0], b[nb * 2 + 1][1],
                        Bs + sw128(off));
            }
            #pragma unroll
            for (int mi = 0; mi < 4; mi++)
                #pragma unroll
                for (int j = 0; j < 4; j++)
                    mma_fp16(acc[mi][j], a[mi], b[j]);
        }
    }
    __syncthreads();   // smem stages now reusable as epilogue scratch

    // ---- epilogue: gates -> smem, fused cell update ------------------------
    float* gates = (float*)smem;                  // 128 rows x GPITCH floats
    const int g = lid >> 2, tg = lid & 3;

    {
        const int clb = wn * 32;
        #pragma unroll
        for (int mi = 0; mi < 4; mi++) {
            const int r = wm * 64 + mi * 16 + g;
            #pragma unroll
            for (int j = 0; j < 4; j++) {
                const int cl = clb + j * 8 + 2 * tg;
                *(float2*)&gates[r * GPITCH + cl]       = make_float2(acc[mi][j][0], acc[mi][j][1]);
                *(float2*)&gates[(r + 8) * GPITCH + cl] = make_float2(acc[mi][j][2], acc[mi][j][3]);
            }
        }
    }
    __syncthreads();

    #pragma unroll 2
    for (int jj = 0; jj < 16; jj++) {
        const int idx = tid + jj * NTHREADS;       // 4096 = 128 rows x 32 units
        const int row = idx >> 5, u = idx & 31;
        const int ug = u0 + u;                     // global unit 0..1023
        const int b = m0 + row;

        float4 gv = *(float4*)&gates[row * GPITCH + 4 * u];
        float4 bs = smB[u];
        float4 w0 = smW0[u];
        float4 w1 = smW1[u];

        float prev = (t > 0) ? out[b * TT + (t - 1)] : 0.0f;   // includes fc_b
        const float fdv = future_fd[b * TT + t];

        float gi = gv.x + bs.x + prev * w0.x + fdv * w1.x;
        float gf = gv.y + bs.y + prev * w0.y + fdv * w1.y;
        float gg = gv.z + bs.z + prev * w0.z + fdv * w1.z;
        float go = gv.w + bs.w + prev * w0.w + fdv * w1.w;

        float co = g_c[(size_t)b * HH + ug];
        float cn = sigf(gf) * co + sigf(gi) * tanh_f(gg);
        float h  = sigf(go) * tanh_f(cn);
        g_c[(size_t)b * HH + ug] = cn;
        Adst[(size_t)b * KE + ug] = __float2half(h);

        float fcp = h * smFc[u];
        #pragma unroll
        for (int o = 16; o; o >>= 1) fcp += __shfl_down_sync(0xFFFFFFFFu, fcp, o);
        if (lid == 0) atomicAdd(&out[b * TT + t], fcp);
    }

    // ---- signal: this CTA's h/out/c contributions are globally visible -----
    __threadfence();          // every thread fences its own stores
    __syncthreads();
    if (tid == 0) atomicAdd(&g_flags[t * NBX + blockIdx.x], 1);
}

// ---------------------------------------------------------------------------
// Host launcher
// ---------------------------------------------------------------------------
extern "C" void kernel_launch(void* const* d_in, const int* in_sizes, int n_in,
                              void* d_out, int out_size) {
    const float* future_fd = (const float*)d_in[0];
    const float* hidden    = (const float*)d_in[1];
    const float* cell      = (const float*)d_in[2];
    const float* W_ih      = (const float*)d_in[3];
    const float* W_hh      = (const float*)d_in[4];
    const float* b_ih      = (const float*)d_in[5];
    const float* b_hh      = (const float*)d_in[6];
    const float* fc_W      = (const float*)d_in[7];
    const float* fc_b      = (const float*)d_in[8];
    float* out = (float*)d_out;

    cudaFuncSetAttribute(step_kernel, cudaFuncAttributeMaxDynamicSharedMemorySize, SMEM_BYTES);

    prep_weights<<<(N4 * HH) / 256, 256>>>(W_hh, W_ih, b_ih, b_hh, fc_W);
    prep_state<<<(BATCH * HH) / 256, 256>>>(hidden, cell, out, fc_b);

    cudaLaunchAttribute pdl_attr;
    pdl_attr.id = cudaLaunchAttributeProgrammaticStreamSerialization;
    pdl_attr.val.programmaticStreamSerializationAllowed = 1;

    for (int t = 0; t < TT; t++) {
        cudaLaunchConfig_t cfg = {};
        cfg.gridDim = dim3(BATCH / TM, N4 / TN, 1);
        cfg.blockDim = dim3(NTHREADS, 1, 1);
        cfg.dynamicSmemBytes = SMEM_BYTES;
        cfg.stream = 0;
        if (t > 0) { cfg.attrs = &pdl_attr; cfg.numAttrs = 1; }   // t=0 plain: prep must fully finish
        cudaLaunchKernelEx(&cfg, step_kernel, t, future_fd, out);
    }
}

// round 13
// speedup vs baseline: 1.0780x; 1.0780x over previous
#include <cuda_runtime.h>
#include <cuda_fp16.h>
#include <cstdint>

// ============================================================================
// LSTM decoder, B=2048, T=32, H=1024, inference path (pred feedback).
// sm_100: fp16 mma.sync GEMM + cp.async 3-stage pipeline, 2 CTAs/SM (R5
// champion GEMM config) + R10 PDL overhead cuts + R12 trims:
//  - PDL grid-wide wait (R11's fine-grained flags REVERTED: slower).
//  - Pre-wait prefetch of ALL 3 B stages (B0,B1,B2) + const staging; A loads
//    after griddepcontrol.wait. Group order: {B0}{B1}{B2}|wait|{A0}{A1},
//    c=0 issues {A2} alone, c>=1 issues fused {A,B}(c+2); wait_group 1 steady.
//  - Epilogue unroll 4 for more L2-latency MLP.
//  - predsum folded into d_out (init = fc_b in prep; prev read from d_out).
// W columns permuted: col n -> (unit n>>2, gate n&3), gate order i,f,g,o.
// h double-buffered across steps (cross-CTA race fix).
// (R13 = R12 resubmitted: R12 bench was an infra container failure, never ran.)
// ============================================================================

#define BATCH 2048
#define TT    32
#define HH    1024
#define N4    4096
#define KE    1024            // K = H (single fp16 term)
#define TM    128             // M tile
#define TN    128             // N tile
#define KC    64              // K chunk (fp16) = 128 bytes
#define NCH   (KE / KC)       // 16
#define NTHREADS 256
#define STAGES 3
#define STAGE_BYTES 32768     // A 16KB + B 16KB
#define STAGING_BYTES 2048
#define SMEM_BYTES  (1024 + STAGES * STAGE_BYTES + STAGING_BYTES)  // ~99KB
#define GPITCH 132            // gates smem pitch (floats), conflict-free

// Scratch (device globals; no allocation allowed)
__device__ __align__(256) __half g_Wext[(size_t)N4 * KE];        // 8 MB
__device__ __align__(256) __half g_Aext[2][(size_t)BATCH * KE];  // 2 x 4 MB
__device__ __align__(256) float g_c[(size_t)BATCH * HH];         // 8 MB
__device__ __align__(256) float g_bias[N4];
__device__ __align__(256) float g_w0[N4];
__device__ __align__(256) float g_w1[N4];
__device__ __align__(256) float g_fcW[HH];

// ---------------------------------------------------------------------------
// helpers
// ---------------------------------------------------------------------------
__device__ __forceinline__ uint32_t smem_u32(const void* p) {
    uint32_t a;
    asm("{ .reg .u64 t; cvta.to.shared.u64 t, %1; cvt.u32.u64 %0, t; }" : "=r"(a) : "l"(p));
    return a;
}
__device__ __forceinline__ void cp_async16(uint32_t dst, const void* src) {
    asm volatile("cp.async.cg.shared.global [%0], [%1], 16;" :: "r"(dst), "l"(src) : "memory");
}
__device__ __forceinline__ void cp_commit() {
    asm volatile("cp.async.commit_group;" ::: "memory");
}
__device__ __forceinline__ uint32_t sw128(uint32_t off) {
    return off ^ ((off >> 3) & 0x70u);
}
__device__ __forceinline__ void ldsm_x4(uint32_t& r0, uint32_t& r1, uint32_t& r2, uint32_t& r3,
                                        uint32_t addr) {
    asm volatile("ldmatrix.sync.aligned.m8n8.x4.shared.b16 {%0,%1,%2,%3}, [%4];"
                 : "=r"(r0), "=r"(r1), "=r"(r2), "=r"(r3) : "r"(addr));
}
__device__ __forceinline__ void mma_fp16(float* d, const uint32_t* a, const uint32_t* b) {
    asm volatile(
        "mma.sync.aligned.m16n8k16.row.col.f32.f16.f16.f32 "
        "{%0,%1,%2,%3}, {%4,%5,%6,%7}, {%8,%9}, {%0,%1,%2,%3};"
        : "+f"(d[0]), "+f"(d[1]), "+f"(d[2]), "+f"(d[3])
        : "r"(a[0]), "r"(a[1]), "r"(a[2]), "r"(a[3]), "r"(b[0]), "r"(b[1]));
}
__device__ __forceinline__ float sigf(float x) {
    return __fdividef(1.0f, 1.0f + __expf(-x));
}
__device__ __forceinline__ float tanh_f(float x) {
    float xc = fminf(fmaxf(x, -15.0f), 15.0f);
    float e = __expf(2.0f * xc);
    return 1.0f - __fdividef(2.0f, e + 1.0f);
}

// ---------------------------------------------------------------------------
// Prep kernels
// ---------------------------------------------------------------------------
__global__ void prep_weights(const float* __restrict__ W_hh, const float* __restrict__ W_ih,
                             const float* __restrict__ b_ih, const float* __restrict__ b_hh,
                             const float* __restrict__ fc_W) {
    int idx = blockIdx.x * blockDim.x + threadIdx.x;   // 0 .. 4096*1024-1
    int n = idx >> 10, k = idx & 1023;
    int r = (n & 3) * HH + (n >> 2);                   // col n -> orig W_hh row
    g_Wext[(size_t)n * KE + k] = __float2half(W_hh[(size_t)r * HH + k]);
    if (idx < N4) {
        int rr = (idx & 3) * HH + (idx >> 2);
        g_bias[idx] = b_ih[rr] + b_hh[rr];
        g_w0[idx] = W_ih[rr * 2 + 0];
        g_w1[idx] = W_ih[rr * 2 + 1];
    }
    if (idx < HH) g_fcW[idx] = fc_W[idx];
}

__global__ void prep_state(const float* __restrict__ hidden, const float* __restrict__ cell,
                           float* __restrict__ out, const float* __restrict__ fc_b) {
    int idx = blockIdx.x * blockDim.x + threadIdx.x;   // 0 .. 2048*1024-1
    g_c[idx] = cell[idx];
    g_Aext[0][idx] = __float2half(hidden[idx]);
    if (idx < BATCH * TT) out[idx] = fc_b[0];          // predsum accumulates on top
}

// ---------------------------------------------------------------------------
// Step kernel: GEMM (tile 128x128, K=1024) + fused LSTM cell epilogue
// 256 threads = 8 warps; warp tile 64x32: warp_m = wid&1, warp_n = wid>>1.
// ---------------------------------------------------------------------------
__global__ void __launch_bounds__(NTHREADS, 2)
step_kernel(int t, const float* __restrict__ future_fd, float* __restrict__ out) {
    const __half* __restrict__ Asrc = g_Aext[t & 1];
    __half* __restrict__ Adst = g_Aext[(t + 1) & 1];

    extern __shared__ char smem_raw[];
    uint32_t sb = smem_u32(smem_raw);
    uint32_t ab = (sb + 1023u) & ~1023u;
    char* smem = smem_raw + (ab - sb);
    const uint32_t tiles = ab;

    const int tid = threadIdx.x;
    const int wid = tid >> 5;
    const int lid = tid & 31;
    const int wm = wid & 1;          // 0..1  (64-row block)
    const int wn = wid >> 1;         // 0..3  (32-col block)
    const int m0 = blockIdx.x * TM;
    const int n0 = blockIdx.y * TN;
    const int u0 = n0 >> 2;          // first unit of this CTA (32 units)

    // ---- const staging (step-invariant: safe pre-wait) ---------------------
    float4* smB  = (float4*)(smem + STAGES * STAGE_BYTES);   // [32]
    float4* smW0 = smB + 32;
    float4* smW1 = smB + 64;
    float*  smFc = (float*)(smB + 96);                        // [32]
    if (tid < 32)        smB[tid]        = ((const float4*)g_bias)[u0 + tid];
    else if (tid < 64)   smW0[tid - 32]  = ((const float4*)g_w0)[u0 + tid - 32];
    else if (tid < 96)   smW1[tid - 64]  = ((const float4*)g_w1)[u0 + tid - 64];
    else if (tid < 128)  smFc[tid - 96]  = g_fcW[u0 + tid - 96];

    // ---- split chunk loaders ----------------------------------------------
    auto load_A = [&](int c, int s) {
        const int k0 = c * KC;
        const uint32_t base = tiles + s * STAGE_BYTES;
        #pragma unroll
        for (int j = 0; j < 4; j++) {
            int li = tid + j * NTHREADS;
            int ri = li >> 3, q = li & 7;
            uint32_t dst = base + sw128((uint32_t)(ri * 128 + q * 16));
            cp_async16(dst, Asrc + ((size_t)(m0 + ri) * KE + k0 + q * 8));
        }
    };
    auto load_B = [&](int c, int s) {
        const int k0 = c * KC;
        const uint32_t base = tiles + s * STAGE_BYTES + 16384;
        #pragma unroll
        for (int j = 0; j < 4; j++) {
            int li = tid + j * NTHREADS;
            int ri = li >> 3, q = li & 7;
            uint32_t dst = base + sw128((uint32_t)(ri * 128 + q * 16));
            cp_async16(dst, g_Wext + ((size_t)(n0 + ri) * KE + k0 + q * 8));
        }
    };

    // ---- PDL prologue: ALL weight stages prefetch pre-wait -----------------
    load_B(0, 0); cp_commit();                 // group: B0
    load_B(1, 1); cp_commit();                 // group: B1
    load_B(2, 2); cp_commit();                 // group: B2
    asm volatile("griddepcontrol.wait;" ::: "memory");
    load_A(0, 0); cp_commit();                 // group: A0
    load_A(1, 1); cp_commit();                 // group: A1

    // ---- lane constants for ldmatrix addressing ----------------------------
    const int a_lr = lid & 15;
    const int a_ch = (lid >> 4) << 4;
    const int b_nr = (lid & 7) + ((lid >> 4) << 3);
    const int b_ch = ((lid >> 3) & 1) << 4;

    float acc[4][4][4];
    #pragma unroll
    for (int i = 0; i < 4; i++)
        #pragma unroll
        for (int j = 0; j < 4; j++)
            #pragma unroll
            for (int r = 0; r < 4; r++) acc[i][j][r] = 0.0f;

    #pragma unroll 1
    for (int c = 0; c < NCH; c++) {
        // c=0: pending {B0,B1,B2,A0,A1}; wait_group 1 retires B0-B2,A0.
        // c=1: retires A1 (A2 may remain). c>=2 steady: retires chunk c's group.
        if (c < NCH - 2) asm volatile("cp.async.wait_group 1;" ::: "memory");
        else             asm volatile("cp.async.wait_group 0;" ::: "memory");
        __syncthreads();

        if (c == 0)              { load_A(2, 2); cp_commit(); }              // B2 already resident
        else if (c + 2 < NCH)    { load_A(c + 2, (c + 2) % STAGES);
                                   load_B(c + 2, (c + 2) % STAGES); cp_commit(); }

        const uint32_t As = tiles + (c % STAGES) * STAGE_BYTES;
        const uint32_t Bs = As + 16384;

        #pragma unroll
        for (int ks = 0; ks < 4; ks++) {
            uint32_t a[4][4], b[4][2];
            #pragma unroll
            for (int mi = 0; mi < 4; mi++) {
                uint32_t off = (uint32_t)((wm * 64 + mi * 16 + a_lr) * 128 + ks * 32 + a_ch);
                ldsm_x4(a[mi][0], a[mi][1], a[mi][2], a[mi][3], As + sw128(off));
            }
            #pragma unroll
            for (int nb = 0; nb < 2; nb++) {
                uint32_t off = (uint32_t)((wn * 32 + nb * 16 + b_nr) * 128 + ks * 32 + b_ch);
                ldsm_x4(b[nb * 2][0], b[nb * 2][1], b[nb * 2 + 1][0], b[nb * 2 + 1][1],
                        Bs + sw128(off));
            }
            #pragma unroll
            for (int mi = 0; mi < 4; mi++)
                #pragma unroll
                for (int j = 0; j < 4; j++)
                    mma_fp16(acc[mi][j], a[mi], b[j]);
        }
    }
    __syncthreads();   // smem stages now reusable as epilogue scratch

    // Next step's CTAs spin up and prefetch weights while we run the epilogue.
    asm volatile("griddepcontrol.launch_dependents;");

    // ---- epilogue: gates -> smem, fused cell update ------------------------
    float* gates = (float*)smem;                  // 128 rows x GPITCH floats
    const int g = lid >> 2, tg = lid & 3;

    {
        const int clb = wn * 32;
        #pragma unroll
        for (int mi = 0; mi < 4; mi++) {
            const int r = wm * 64 + mi * 16 + g;
            #pragma unroll
            for (int j = 0; j < 4; j++) {
                const int cl = clb + j * 8 + 2 * tg;
                *(float2*)&gates[r * GPITCH + cl]       = make_float2(acc[mi][j][0], acc[mi][j][1]);
                *(float2*)&gates[(r + 8) * GPITCH + cl] = make_float2(acc[mi][j][2], acc[mi][j][3]);
            }
        }
    }
    __syncthreads();

    #pragma unroll 4
    for (int jj = 0; jj < 16; jj++) {
        const int idx = tid + jj * NTHREADS;       // 4096 = 128 rows x 32 units
        const int row = idx >> 5, u = idx & 31;
        const int ug = u0 + u;                     // global unit 0..1023
        const int b = m0 + row;

        float4 gv = *(float4*)&gates[row * GPITCH + 4 * u];
        float4 bs = smB[u];
        float4 w0 = smW0[u];
        float4 w1 = smW1[u];

        float prev = (t > 0) ? out[b * TT + (t - 1)] : 0.0f;   // includes fc_b
        const float fdv = future_fd[b * TT + t];

        float gi = gv.x + bs.x + prev * w0.x + fdv * w1.x;
        float gf = gv.y + bs.y + prev * w0.y + fdv * w1.y;
        float gg = gv.z + bs.z + prev * w0.z + fdv * w1.z;
        float go = gv.w + bs.w + prev * w0.w + fdv * w1.w;

        float co = g_c[(size_t)b * HH + ug];
        float cn = sigf(gf) * co + sigf(gi) * tanh_f(gg);
        float h  = sigf(go) * tanh_f(cn);
        g_c[(size_t)b * HH + ug] = cn;
        Adst[(size_t)b * KE + ug] = __float2half(h);

        float fcp = h * smFc[u];
        #pragma unroll
        for (int o = 16; o; o >>= 1) fcp += __shfl_down_sync(0xFFFFFFFFu, fcp, o);
        if (lid == 0) atomicAdd(&out[b * TT + t], fcp);
    }
}

// ---------------------------------------------------------------------------
// Host launcher
// ---------------------------------------------------------------------------
extern "C" void kernel_launch(void* const* d_in, const int* in_sizes, int n_in,
                              void* d_out, int out_size) {
    const float* future_fd = (const float*)d_in[0];
    const float* hidden    = (const float*)d_in[1];
    const float* cell      = (const float*)d_in[2];
    const float* W_ih      = (const float*)d_in[3];
    const float* W_hh      = (const float*)d_in[4];
    const float* b_ih      = (const float*)d_in[5];
    const float* b_hh      = (const float*)d_in[6];
    const float* fc_W      = (const float*)d_in[7];
    const float* fc_b      = (const float*)d_in[8];
    float* out = (float*)d_out;

    cudaFuncSetAttribute(step_kernel, cudaFuncAttributeMaxDynamicSharedMemorySize, SMEM_BYTES);

    prep_weights<<<(N4 * HH) / 256, 256>>>(W_hh, W_ih, b_ih, b_hh, fc_W);
    prep_state<<<(BATCH * HH) / 256, 256>>>(hidden, cell, out, fc_b);

    cudaLaunchAttribute pdl_attr;
    pdl_attr.id = cudaLaunchAttributeProgrammaticStreamSerialization;
    pdl_attr.val.programmaticStreamSerializationAllowed = 1;

    for (int t = 0; t < TT; t++) {
        cudaLaunchConfig_t cfg = {};
        cfg.gridDim = dim3(BATCH / TM, N4 / TN, 1);
        cfg.blockDim = dim3(NTHREADS, 1, 1);
        cfg.dynamicSmemBytes = SMEM_BYTES;
        cfg.stream = 0;
        if (t > 0) { cfg.attrs = &pdl_attr; cfg.numAttrs = 1; }   // t=0 plain: prep must fully finish
        cudaLaunchKernelEx(&cfg, step_kernel, t, future_fd, out);
    }
}